// round 2
// baseline (speedup 1.0000x reference)
#include <cuda_runtime.h>
#include <cuda_bf16.h>

#define EPS_F 1e-6f

constexpr int C_DIM    = 128;
constexpr int T_TOK    = 16;
constexpr int NTHREADS = 384;
constexpr int B_BATCH  = 4;
constexpr int N_TOK    = 1024;
constexpr int TOKENS   = B_BATCH * N_TOK;   // 4096

// scratch for V (Ri needs raw V; K is re-read from the Si output region)
__device__ __align__(16) float g_V[TOKENS * C_DIM];

__device__ __forceinline__ float feature_map(float x) {
    return x > 0.0f ? x + 1.0f : __expf(x);
}

// ---------------------------------------------------------------------------
// Kernel 1: projections + s; writes RLSA, Si(=K), and V scratch. ~3 MB traffic.
// ---------------------------------------------------------------------------
__global__ __launch_bounds__(NTHREADS, 2)
void rlsa_compute_kernel(const float* __restrict__ feat,
                         const float* __restrict__ wq, const float* __restrict__ bq,
                         const float* __restrict__ wk, const float* __restrict__ bk,
                         const float* __restrict__ wv, const float* __restrict__ bv,
                         float* __restrict__ out)
{
    __shared__ __align__(16) float xs[T_TOK][C_DIM];
    __shared__ __align__(16) float qs[T_TOK][C_DIM];
    __shared__ __align__(16) float ks[T_TOK][C_DIM];
    __shared__ __align__(16) float vs[T_TOK][C_DIM];
    __shared__ float s_sm[T_TOK];

    const int tid = threadIdx.x;
    const int g0  = blockIdx.x * T_TOK;
    const int b   = g0 >> 10;
    const int n0  = g0 & (N_TOK - 1);

    // gather x tile: xs[t][i] = feature[b, i, n0+t]
    for (int idx = tid; idx < T_TOK * C_DIM; idx += NTHREADS) {
        int t = idx >> 7;
        int i = idx & (C_DIM - 1);
        xs[t][i] = feat[(((size_t)(b * C_DIM + i)) << 10) + (size_t)(n0 + t)];
    }
    __syncthreads();

    // projections: warpgroup per {q,k,v}, thread per output channel
    {
        const int proj = tid >> 7;
        const int o    = tid & (C_DIM - 1);
        const float* W  = (proj == 0) ? wq : (proj == 1) ? wk : wv;
        const float* Bp = (proj == 0) ? bq : (proj == 1) ? bk : bv;

        float acc[T_TOK];
        const float bias = __ldg(&Bp[o]);
        #pragma unroll
        for (int t = 0; t < T_TOK; t++) acc[t] = bias;

        const float4* Wr = reinterpret_cast<const float4*>(W + (size_t)o * C_DIM);
        #pragma unroll 2
        for (int i4 = 0; i4 < C_DIM / 4; i4++) {
            const float4 w = __ldg(&Wr[i4]);
            #pragma unroll
            for (int t = 0; t < T_TOK; t++) {
                const float4 xv = reinterpret_cast<const float4*>(xs[t])[i4];
                acc[t] = fmaf(w.x, xv.x, acc[t]);
                acc[t] = fmaf(w.y, xv.y, acc[t]);
                acc[t] = fmaf(w.z, xv.z, acc[t]);
                acc[t] = fmaf(w.w, xv.w, acc[t]);
            }
        }

        float* dst = (proj == 0) ? &qs[0][0] : (proj == 1) ? &ks[0][0] : &vs[0][0];
        if (proj < 2) {
            #pragma unroll
            for (int t = 0; t < T_TOK; t++) dst[t * C_DIM + o] = feature_map(acc[t]);
        } else {
            #pragma unroll
            for (int t = 0; t < T_TOK; t++) dst[t * C_DIM + o] = acc[t];
        }
    }
    __syncthreads();

    // per-token s = dot(Q, K)
    {
        const int warp = tid >> 5;
        const int lane = tid & 31;
        for (int t = warp; t < T_TOK; t += NTHREADS / 32) {
            float p = 0.0f;
            #pragma unroll
            for (int j = 0; j < C_DIM; j += 32)
                p = fmaf(qs[t][lane + j], ks[t][lane + j], p);
            #pragma unroll
            for (int off = 16; off; off >>= 1)
                p += __shfl_down_sync(0xffffffffu, p, off);
            if (lane == 0) s_sm[t] = p;
        }
    }
    __syncthreads();

    // small outputs: RLSA, Si(=K), V scratch  (16 tokens * 3 * 32 float4 = 1536)
    const size_t RLSA_SIZE = (size_t)TOKENS * C_DIM;
    float* rlsa = out;
    float* si   = out + RLSA_SIZE + RLSA_SIZE * (size_t)C_DIM;

    for (int idx = tid; idx < T_TOK * 32; idx += NTHREADS) {
        const int t  = idx >> 5;
        const int mv = idx & 31;
        const int g  = g0 + t;
        const float s  = s_sm[t];
        const float sc = s / (s + EPS_F);
        const float4 v = reinterpret_cast<const float4*>(vs[t])[mv];
        const float4 k = reinterpret_cast<const float4*>(ks[t])[mv];
        reinterpret_cast<float4*>(rlsa + (size_t)g * C_DIM)[mv] =
            make_float4(sc * v.x, sc * v.y, sc * v.z, sc * v.w);
        reinterpret_cast<float4*>(si + (size_t)g * C_DIM)[mv] = k;
        reinterpret_cast<float4*>(g_V + (size_t)g * C_DIM)[mv] = v;
    }
}

// ---------------------------------------------------------------------------
// Kernel 2: pure Ri streamer. One block per token; 256 threads; each thread
// owns one fixed m (float4) and issues 16 independent 512B-coalesced STG.128.
// ---------------------------------------------------------------------------
__global__ __launch_bounds__(256, 8)
void ri_store_kernel(const float* __restrict__ ksrc,   // Si region of out
                     const float* __restrict__ vsrc,   // g_V
                     float* __restrict__ ri)
{
    __shared__ float  ksm[C_DIM];
    __shared__ __align__(16) float4 vsm[C_DIM / 4];

    const int g   = blockIdx.x;
    const int tid = threadIdx.x;

    if (tid < C_DIM) {
        ksm[tid] = ksrc[(size_t)g * C_DIM + tid];
    } else if (tid < C_DIM + 32) {
        vsm[tid - C_DIM] =
            reinterpret_cast<const float4*>(vsrc + (size_t)g * C_DIM)[tid - C_DIM];
    }
    __syncthreads();

    const int m  = tid & 31;       // float4 column, fixed per thread
    const int c0 = tid >> 5;       // 0..7
    const float4 v = vsm[m];
    float4* rp = reinterpret_cast<float4*>(ri + (size_t)g * (C_DIM * C_DIM));

    #pragma unroll
    for (int i = 0; i < 16; i++) {
        const int c = c0 + i * 8;
        const float kc = ksm[c];   // warp-uniform broadcast
        rp[c * 32 + m] = make_float4(kc * v.x, kc * v.y, kc * v.z, kc * v.w);
    }
}

extern "C" void kernel_launch(void* const* d_in, const int* in_sizes, int n_in,
                              void* d_out, int out_size)
{
    const float* feat = (const float*)d_in[0];
    const float* wq   = (const float*)d_in[1];
    const float* bq   = (const float*)d_in[2];
    const float* wk   = (const float*)d_in[3];
    const float* bk   = (const float*)d_in[4];
    const float* wv   = (const float*)d_in[5];
    const float* bv   = (const float*)d_in[6];
    float* out = (float*)d_out;

    const size_t RLSA_SIZE = (size_t)TOKENS * C_DIM;
    float* ri = out + RLSA_SIZE;
    float* si = out + RLSA_SIZE + RLSA_SIZE * (size_t)C_DIM;

    float* vscratch;
    cudaGetSymbolAddress((void**)&vscratch, g_V);

    rlsa_compute_kernel<<<TOKENS / T_TOK, NTHREADS>>>(feat, wq, bq, wk, bk, wv, bv, out);
    ri_store_kernel<<<TOKENS, 256>>>(si, vscratch, ri);
}

// round 3
// speedup vs baseline: 1.0910x; 1.0910x over previous
#include <cuda_runtime.h>
#include <cuda_bf16.h>
#include <cstdint>

#define EPS_F 1e-6f

constexpr int C_DIM    = 128;
constexpr int T_TOK    = 8;      // tokens per block
constexpr int NTHREADS = 128;    // one thread per output channel o
constexpr int B_BATCH  = 4;
constexpr int N_TOK    = 1024;
constexpr int TOKENS   = B_BATCH * N_TOK;   // 4096
constexpr int NBLOCKS  = TOKENS / T_TOK;    // 512

// Transposed/packed weights: Wp[proj][i4][o] = float4(W[o][4*i4 .. 4*i4+3])
// Flat index: ((proj*32 + i4)*128 + o)*4 + r
__device__ __align__(16) float g_Wp[3 * 32 * C_DIM * 4];

__device__ __forceinline__ float feature_map(float x) {
    return x > 0.0f ? x + 1.0f : __expf(x);   // elu(x)+1
}

__device__ __forceinline__ void fma_f32x2(unsigned long long& acc,
                                          unsigned long long a,
                                          unsigned long long b) {
    asm("fma.rn.f32x2 %0, %1, %2, %0;" : "+l"(acc) : "l"(a), "l"(b));
}

__device__ __forceinline__ float unpack_sum(unsigned long long acc) {
    float lo, hi;
    asm("mov.b64 {%0, %1}, %2;" : "=f"(lo), "=f"(hi) : "l"(acc));
    return lo + hi;
}

// ---------------------------------------------------------------------------
// Kernel 0: pack/transpose weights (192 KB, ~2 us)
// ---------------------------------------------------------------------------
__global__ void wprep_kernel(const float* __restrict__ wq,
                             const float* __restrict__ wk,
                             const float* __restrict__ wv)
{
    int idx = blockIdx.x * 256 + threadIdx.x;        // 0 .. 49151
    int proj = idx >> 14;
    int rem  = idx & 16383;
    int i4 = rem >> 9;
    int o  = (rem >> 2) & 127;
    int rr = rem & 3;
    const float* W = (proj == 0) ? wq : (proj == 1) ? wk : wv;
    g_Wp[idx] = W[o * C_DIM + i4 * 4 + rr];
}

// ---------------------------------------------------------------------------
// Kernel 1: fused projections + feature map + s + all output streams.
// 512 blocks x 128 threads; thread = output channel o; 8 tokens per block.
// ---------------------------------------------------------------------------
__global__ __launch_bounds__(NTHREADS, 8)
void rlsa_fused_kernel(const float* __restrict__ feat,
                       const float* __restrict__ bq,
                       const float* __restrict__ bk,
                       const float* __restrict__ bv,
                       float* __restrict__ out)
{
    __shared__ __align__(16) float xs[T_TOK][C_DIM];
    __shared__ __align__(16) float qs[T_TOK][C_DIM];
    __shared__ __align__(16) float ks[T_TOK][C_DIM];
    __shared__ __align__(16) float vs[T_TOK][C_DIM];
    __shared__ float s_sm[T_TOK];

    const int tid = threadIdx.x;
    const int g0  = blockIdx.x * T_TOK;
    const int b   = g0 >> 10;
    const int n0  = g0 & (N_TOK - 1);

    // ---- gather x tile: xs[t][i] = feature[b, i, n0+t] ----
    #pragma unroll
    for (int idx = tid; idx < T_TOK * C_DIM; idx += NTHREADS) {
        int t = idx >> 7;
        int i = idx & (C_DIM - 1);
        xs[t][i] = feat[(((size_t)(b * C_DIM + i)) << 10) + (size_t)(n0 + t)];
    }
    __syncthreads();

    // ---- projections: thread o computes q/k/v[t][o] with packed f32x2 ----
    const int o = tid;
    {
        const ulonglong2* Wbase = reinterpret_cast<const ulonglong2*>(g_Wp) + o;

        #pragma unroll
        for (int proj = 0; proj < 3; proj++) {
            const ulonglong2* W2 = Wbase + proj * (32 * C_DIM);
            const float bias = (proj == 0) ? __ldg(&bq[o])
                             : (proj == 1) ? __ldg(&bk[o]) : __ldg(&bv[o]);

            unsigned long long acc[T_TOK];
            #pragma unroll
            for (int t = 0; t < T_TOK; t++) acc[t] = 0ull;  // (0.0f, 0.0f)

            #pragma unroll 4
            for (int i4 = 0; i4 < 32; i4++) {
                const ulonglong2 w = W2[i4 * C_DIM];        // coalesced 512B/warp
                #pragma unroll
                for (int t = 0; t < T_TOK; t++) {
                    const ulonglong2 x =
                        reinterpret_cast<const ulonglong2*>(xs[t])[i4]; // broadcast
                    fma_f32x2(acc[t], w.x, x.x);
                    fma_f32x2(acc[t], w.y, x.y);
                }
            }

            if (proj == 0) {
                #pragma unroll
                for (int t = 0; t < T_TOK; t++)
                    qs[t][o] = feature_map(unpack_sum(acc[t]) + bias);
            } else if (proj == 1) {
                #pragma unroll
                for (int t = 0; t < T_TOK; t++)
                    ks[t][o] = feature_map(unpack_sum(acc[t]) + bias);
            } else {
                #pragma unroll
                for (int t = 0; t < T_TOK; t++)
                    vs[t][o] = unpack_sum(acc[t]) + bias;
            }
        }
    }
    __syncthreads();

    // ---- s[t] = dot(Q[t], K[t]) : warp per token round-robin ----
    {
        const int warp = tid >> 5;
        const int lane = tid & 31;
        for (int t = warp; t < T_TOK; t += NTHREADS / 32) {
            float p = 0.0f;
            #pragma unroll
            for (int j = 0; j < C_DIM; j += 32)
                p = fmaf(qs[t][lane + j], ks[t][lane + j], p);
            #pragma unroll
            for (int off = 16; off; off >>= 1)
                p += __shfl_down_sync(0xffffffffu, p, off);
            if (lane == 0) s_sm[t] = p;
        }
    }
    __syncthreads();

    // ---- streams: RLSA | Ri | Si ----
    const size_t RLSA_SIZE = (size_t)TOKENS * C_DIM;
    float* rlsa = out;
    float* ri   = out + RLSA_SIZE;
    float* si   = out + RLSA_SIZE + RLSA_SIZE * (size_t)C_DIM;

    const int m  = tid & 31;   // float4 column within a Ri row
    const int c0 = tid >> 5;   // 0..3

    #pragma unroll 1
    for (int t = 0; t < T_TOK; t++) {
        const int g = g0 + t;
        const float s  = s_sm[t];
        const float sc = s / (s + EPS_F);
        const float4 v = reinterpret_cast<const float4*>(vs[t])[m];

        if (c0 == 0) {
            reinterpret_cast<float4*>(rlsa + (size_t)g * C_DIM)[m] =
                make_float4(sc * v.x, sc * v.y, sc * v.z, sc * v.w);
        } else if (c0 == 1) {
            reinterpret_cast<float4*>(si + (size_t)g * C_DIM)[m] =
                reinterpret_cast<const float4*>(ks[t])[m];
        }

        float4* rp = reinterpret_cast<float4*>(ri + (size_t)g * (C_DIM * C_DIM));
        #pragma unroll
        for (int j = 0; j < 32; j++) {
            const int c = c0 + j * 4;
            const float kc = ks[t][c];          // warp-uniform broadcast
            rp[c * 32 + m] =
                make_float4(kc * v.x, kc * v.y, kc * v.z, kc * v.w);
        }
    }
}

extern "C" void kernel_launch(void* const* d_in, const int* in_sizes, int n_in,
                              void* d_out, int out_size)
{
    const float* feat = (const float*)d_in[0];
    const float* wq   = (const float*)d_in[1];
    const float* bq   = (const float*)d_in[2];
    const float* wk   = (const float*)d_in[3];
    const float* bk   = (const float*)d_in[4];
    const float* wv   = (const float*)d_in[5];
    const float* bv   = (const float*)d_in[6];
    float* out = (float*)d_out;

    wprep_kernel<<<192, 256>>>(wq, wk, wv);
    rlsa_fused_kernel<<<NBLOCKS, NTHREADS>>>(feat, bq, bk, bv, out);
}

// round 4
// speedup vs baseline: 1.2217x; 1.1199x over previous
#include <cuda_runtime.h>
#include <cuda_bf16.h>
#include <cstdint>

#define EPS_F 1e-6f

constexpr int C_DIM    = 128;
constexpr int T_TOK    = 4;      // tokens per block (finer -> more resident blocks)
constexpr int NTHREADS = 128;    // one thread per output channel o
constexpr int B_BATCH  = 4;
constexpr int N_TOK    = 1024;
constexpr int TOKENS   = B_BATCH * N_TOK;   // 4096
constexpr int NBLOCKS  = TOKENS / T_TOK;    // 1024

// Transposed/packed weights: Wp[proj][i4][o] = float4(W[o][4*i4 .. 4*i4+3])
__device__ __align__(16) float g_Wp[3 * 32 * C_DIM * 4];

__device__ __forceinline__ float feature_map(float x) {
    return x > 0.0f ? x + 1.0f : __expf(x);   // elu(x)+1
}

__device__ __forceinline__ void fma_f32x2(unsigned long long& acc,
                                          unsigned long long a,
                                          unsigned long long b) {
    asm("fma.rn.f32x2 %0, %1, %2, %0;" : "+l"(acc) : "l"(a), "l"(b));
}

__device__ __forceinline__ float unpack_sum(unsigned long long acc) {
    float lo, hi;
    asm("mov.b64 {%0, %1}, %2;" : "=f"(lo), "=f"(hi) : "l"(acc));
    return lo + hi;
}

// ---------------------------------------------------------------------------
// Kernel 0: pack/transpose weights (192 KB, ~2 us)
// ---------------------------------------------------------------------------
__global__ void wprep_kernel(const float* __restrict__ wq,
                             const float* __restrict__ wk,
                             const float* __restrict__ wv)
{
    int idx = blockIdx.x * 256 + threadIdx.x;        // 0 .. 49151
    int proj = idx >> 14;
    int rem  = idx & 16383;
    int i4 = rem >> 9;
    int o  = (rem >> 2) & 127;
    int rr = rem & 3;
    const float* W = (proj == 0) ? wq : (proj == 1) ? wk : wv;
    g_Wp[idx] = W[o * C_DIM + i4 * 4 + rr];
}

// ---------------------------------------------------------------------------
// Kernel 1: fused projections + feature map + s + all output streams.
// 1024 blocks x 128 threads; thread = output channel o; 4 tokens per block.
// ---------------------------------------------------------------------------
__global__ __launch_bounds__(NTHREADS, 8)
void rlsa_fused_kernel(const float* __restrict__ feat,
                       const float* __restrict__ bq,
                       const float* __restrict__ bk,
                       const float* __restrict__ bv,
                       float* __restrict__ out)
{
    __shared__ __align__(16) float xs[T_TOK][C_DIM];
    __shared__ __align__(16) float qs[T_TOK][C_DIM];
    __shared__ __align__(16) float ks[T_TOK][C_DIM];
    __shared__ __align__(16) float vs[T_TOK][C_DIM];
    __shared__ float s_sm[T_TOK];

    const int tid = threadIdx.x;
    const int g0  = blockIdx.x * T_TOK;
    const int b   = g0 >> 10;
    const int n0  = g0 & (N_TOK - 1);

    // ---- gather x tile: xs[t][i] = feature[b, i, n0+t] ----
    #pragma unroll
    for (int idx = tid; idx < T_TOK * C_DIM; idx += NTHREADS) {
        int t = idx >> 7;
        int i = idx & (C_DIM - 1);
        xs[t][i] = feat[(((size_t)(b * C_DIM + i)) << 10) + (size_t)(n0 + t)];
    }
    __syncthreads();

    // ---- projections: thread o computes q/k/v[t][o] with packed f32x2 ----
    const int o = tid;
    {
        const ulonglong2* Wbase = reinterpret_cast<const ulonglong2*>(g_Wp) + o;

        #pragma unroll
        for (int proj = 0; proj < 3; proj++) {
            const ulonglong2* W2 = Wbase + proj * (32 * C_DIM);
            const float bias = (proj == 0) ? __ldg(&bq[o])
                             : (proj == 1) ? __ldg(&bk[o]) : __ldg(&bv[o]);

            unsigned long long acc[T_TOK];
            #pragma unroll
            for (int t = 0; t < T_TOK; t++) acc[t] = 0ull;  // (0.0f, 0.0f)

            #pragma unroll 8
            for (int i4 = 0; i4 < 32; i4++) {
                const ulonglong2 w = W2[i4 * C_DIM];        // coalesced 512B/warp
                #pragma unroll
                for (int t = 0; t < T_TOK; t++) {
                    const ulonglong2 x =
                        reinterpret_cast<const ulonglong2*>(xs[t])[i4]; // broadcast
                    fma_f32x2(acc[t], w.x, x.x);
                    fma_f32x2(acc[t], w.y, x.y);
                }
            }

            if (proj == 0) {
                #pragma unroll
                for (int t = 0; t < T_TOK; t++)
                    qs[t][o] = feature_map(unpack_sum(acc[t]) + bias);
            } else if (proj == 1) {
                #pragma unroll
                for (int t = 0; t < T_TOK; t++)
                    ks[t][o] = feature_map(unpack_sum(acc[t]) + bias);
            } else {
                #pragma unroll
                for (int t = 0; t < T_TOK; t++)
                    vs[t][o] = unpack_sum(acc[t]) + bias;
            }
        }
    }
    __syncthreads();

    // ---- s[t] = dot(Q[t], K[t]) : warp per token ----
    {
        const int warp = tid >> 5;
        const int lane = tid & 31;
        for (int t = warp; t < T_TOK; t += NTHREADS / 32) {
            float p = 0.0f;
            #pragma unroll
            for (int j = 0; j < C_DIM; j += 32)
                p = fmaf(qs[t][lane + j], ks[t][lane + j], p);
            #pragma unroll
            for (int off = 16; off; off >>= 1)
                p += __shfl_down_sync(0xffffffffu, p, off);
            if (lane == 0) s_sm[t] = p;
        }
    }
    __syncthreads();

    // ---- streams: RLSA | Ri | Si ----
    const size_t RLSA_SIZE = (size_t)TOKENS * C_DIM;
    float* rlsa = out;
    float* ri   = out + RLSA_SIZE;
    float* si   = out + RLSA_SIZE + RLSA_SIZE * (size_t)C_DIM;

    const int m  = tid & 31;   // float4 column within a Ri row
    const int c0 = tid >> 5;   // 0..3

    #pragma unroll 1
    for (int t = 0; t < T_TOK; t++) {
        const int g = g0 + t;
        const float s  = s_sm[t];
        const float sc = s / (s + EPS_F);
        const float4 v = reinterpret_cast<const float4*>(vs[t])[m];

        if (c0 == 0) {
            reinterpret_cast<float4*>(rlsa + (size_t)g * C_DIM)[m] =
                make_float4(sc * v.x, sc * v.y, sc * v.z, sc * v.w);
        } else if (c0 == 1) {
            reinterpret_cast<float4*>(si + (size_t)g * C_DIM)[m] =
                reinterpret_cast<const float4*>(ks[t])[m];
        }

        float4* rp = reinterpret_cast<float4*>(ri + (size_t)g * (C_DIM * C_DIM));
        #pragma unroll
        for (int j = 0; j < 32; j++) {
            const int c = c0 + j * 4;
            const float kc = ks[t][c];          // warp-uniform broadcast
            // streaming store: Ri is write-once, keep weights resident in L2
            __stcs(&rp[c * 32 + m],
                   make_float4(kc * v.x, kc * v.y, kc * v.z, kc * v.w));
        }
    }
}

extern "C" void kernel_launch(void* const* d_in, const int* in_sizes, int n_in,
                              void* d_out, int out_size)
{
    const float* feat = (const float*)d_in[0];
    const float* wq   = (const float*)d_in[1];
    const float* bq   = (const float*)d_in[2];
    const float* wk   = (const float*)d_in[3];
    const float* bk   = (const float*)d_in[4];
    const float* wv   = (const float*)d_in[5];
    const float* bv   = (const float*)d_in[6];
    float* out = (float*)d_out;

    wprep_kernel<<<192, 256>>>(wq, wk, wv);
    rlsa_fused_kernel<<<NBLOCKS, NTHREADS>>>(feat, bq, bk, bv, out);
}